// round 7
// baseline (speedup 1.0000x reference)
#include <cuda_runtime.h>
#include <math.h>
#include <stdint.h>

// ============================================================================
// ComENet-style GNN forward (R7): R6 (395.6us) +
//  - GEMM k-chunk 32 (half the barriers, longer FMA runs)
//  - __ldg on CSR gather streams
//  - branch-skip nnB load in k_geo common path
// ============================================================================

#define NMAX 100480
#define EMAX 1610000
#define GMAX 64
#define SCANB 1024

__device__ unsigned long long g_key1[NMAX];
__device__ unsigned long long g_key2[NMAX];
__device__ unsigned long long g_ekey[EMAX];
__device__ int   g_degin[NMAX];
__device__ int   g_nnA[NMAX];
__device__ int   g_nnB[NMAX];
__device__ int   g_incl[NMAX];
__device__ int   g_bsum[256];
__device__ int   g_boff[256];
__device__ int   g_csroff[NMAX + 1];
__device__ int   g_cursor[NMAX];
__device__ int   g_csrc[EMAX];
__device__ float4 g_cgeo[EMAX];
__device__ float g_bufA[NMAX * 64];   // sum x[src]
__device__ float g_bufU1[NMAX * 64];  // sum relu(geo@c1aw+c1ab)
__device__ float g_bufU2[NMAX * 64];  // sum relu(geo@c2aw+c2ab)
__device__ float g_agg[NMAX * 64];    // sum h1[src]
__device__ float g_h1[NMAX * 64];
__device__ float g_h2[NMAX * 64];
__device__ float g_pool[GMAX * 64];
__device__ int   g_cnt[GMAX];

// ---- packed fp32x2 helpers (Blackwell FFMA2, PTX-only) ---------------------
__device__ __forceinline__ unsigned long long pk2(float v) {
    unsigned long long r;
    unsigned u = __float_as_uint(v);
    asm("mov.b64 %0, {%1, %1};" : "=l"(r) : "r"(u));
    return r;
}
__device__ __forceinline__ void fma2(unsigned long long& d, unsigned long long a,
                                     unsigned long long b, unsigned long long c) {
    asm("fma.rn.f32x2 %0, %1, %2, %3;" : "=l"(d) : "l"(a), "l"(b), "l"(c));
}
__device__ __forceinline__ void unpk2(unsigned long long v, float& lo, float& hi) {
    unsigned a, b;
    asm("mov.b64 {%0, %1}, %2;" : "=r"(a), "=r"(b) : "l"(v));
    lo = __uint_as_float(a);
    hi = __uint_as_float(b);
}

// ---------------------------------------------------------------------------
__global__ void k_init(int n) {
    int i = blockIdx.x * blockDim.x + threadIdx.x;
    if (i < n) {
        g_key1[i] = ~0ULL;
        g_key2[i] = ~0ULL;
        g_degin[i] = 0;
    }
    if (i < GMAX * 64) g_pool[i] = 0.0f;
    if (i < GMAX) g_cnt[i] = 0;
}

// ---------------------------------------------------------------------------
// Edge pass 1: distances, nearest (min d, tie -> min edge idx), in-degree
__global__ void k_edge1(const int* __restrict__ src, const int* __restrict__ dst,
                        const float* __restrict__ pos, int E) {
    int e = blockIdx.x * blockDim.x + threadIdx.x;
    if (e >= E) return;
    int s = src[e], t = dst[e];
    float dx = pos[t * 3 + 0] - pos[s * 3 + 0];
    float dy = pos[t * 3 + 1] - pos[s * 3 + 1];
    float dz = pos[t * 3 + 2] - pos[s * 3 + 2];
    float d = sqrtf(dx * dx + dy * dy + dz * dz);
    unsigned long long key =
        (((unsigned long long)__float_as_uint(d)) << 32) | (unsigned int)e;
    g_ekey[e] = key;
    atomicMin(&g_key1[s], key);
    atomicAdd(&g_degin[t], 1);
}

// Edge pass 2: second nearest (exclude exactly the argmin edge)
__global__ void k_edge2(const int* __restrict__ src, int E) {
    int e = blockIdx.x * blockDim.x + threadIdx.x;
    if (e >= E) return;
    unsigned long long key = g_ekey[e];
    int s = src[e];
    if (key != g_key1[s]) atomicMin(&g_key2[s], key);
}

// Node pass: decode nnA/nnB; per-graph node counts via warp-aggregated atomics.
__global__ void k_node(const int* __restrict__ dst, const int* __restrict__ batch, int N) {
    int i = blockIdx.x * blockDim.x + threadIdx.x;
    int lane = threadIdx.x & 31;
    int b = -1;
    if (i < N) {
        unsigned long long k1 = g_key1[i];
        g_nnA[i] = (k1 != ~0ULL) ? dst[(int)(k1 & 0xffffffffULL)] : i;
        unsigned long long k2 = g_key2[i];
        g_nnB[i] = (k2 != ~0ULL) ? dst[(int)(k2 & 0xffffffffULL)] : i;
        b = batch[i];
    }
    unsigned m = 0xffffffffu;
    int prev = __shfl_up_sync(m, b, 1);
    bool head = (lane == 0) || (b != prev);
    unsigned hm = __ballot_sync(m, head);
    if (head && b >= 0) {
        unsigned rest = (hm >> lane) >> 1;
        int len = rest ? __ffs(rest) : (32 - lane);
        atomicAdd(&g_cnt[b], len);
    }
}

// ---------------------------------------------------------------------------
// 3-kernel exclusive scan of deg_in -> csr offsets + cursors
__global__ void k_scanA(int N) {
    __shared__ int wsum[32];
    int b = blockIdx.x, t = threadIdx.x;
    int i = b * SCANB + t;
    int lane = t & 31, w = t >> 5;
    int v = (i < N) ? g_degin[i] : 0;
    int x = v;
#pragma unroll
    for (int o = 1; o < 32; o <<= 1) {
        int y = __shfl_up_sync(~0u, x, o);
        if (lane >= o) x += y;
    }
    if (lane == 31) wsum[w] = x;
    __syncthreads();
    if (w == 0) {
        int z = wsum[lane];
#pragma unroll
        for (int o = 1; o < 32; o <<= 1) {
            int y = __shfl_up_sync(~0u, z, o);
            if (lane >= o) z += y;
        }
        wsum[lane] = z;
    }
    __syncthreads();
    int off = (w > 0) ? wsum[w - 1] : 0;
    int incl = x + off;
    if (i < N) g_incl[i] = incl;
    if (t == SCANB - 1) g_bsum[b] = incl;
}

__global__ void k_scanB(int nb) {
    __shared__ int sh[256];
    int t = threadIdx.x;
    if (t < nb) sh[t] = g_bsum[t];
    __syncthreads();
    if (t == 0) {
        int run = 0;
        for (int b = 0; b < nb; b++) {
            int v = sh[b];
            sh[b] = run;
            run += v;
        }
    }
    __syncthreads();
    if (t < nb) g_boff[t] = sh[t];
}

__global__ void k_scanC(int N) {
    int i = blockIdx.x * blockDim.x + threadIdx.x;
    if (i >= N) return;
    int b = i / SCANB;
    int tot = g_incl[i] + g_boff[b];
    g_csroff[i + 1] = tot;
    g_cursor[i] = tot - g_degin[i];
    if (i == 0) g_csroff[0] = 0;
}

// ---------------------------------------------------------------------------
// Edge geometry + CSR placement
__global__ void k_geo(const int* __restrict__ src, const int* __restrict__ dst,
                      const float* __restrict__ pos, int E) {
    int e = blockIdx.x * blockDim.x + threadIdx.x;
    if (e >= E) return;
    int s = src[e], t = dst[e];
    float psx = pos[s * 3 + 0], psy = pos[s * 3 + 1], psz = pos[s * 3 + 2];
    float ptx = pos[t * 3 + 0], pty = pos[t * 3 + 1], ptz = pos[t * 3 + 2];

    // branch so the (rare) nnB load is skipped on the common path
    int fi = g_nnA[s];
    if (fi == t) fi = g_nnB[s];
    int fj = g_nnA[t];
    if (fj == s) fj = g_nnB[t];

    float fix = pos[fi * 3 + 0], fiy = pos[fi * 3 + 1], fiz = pos[fi * 3 + 2];
    float fjx = pos[fj * 3 + 0], fjy = pos[fj * 3 + 1], fjz = pos[fj * 3 + 2];

    float rx = ptx - psx, ry = pty - psy, rz = ptz - psz;
    float d = sqrtf(rx * rx + ry * ry + rz * rz);

    const float CLO = -1.0f + 1e-8f;
    const float CHI = 1.0f - 1e-8f;
    float ctheta = rz / (d + 1e-8f);
    ctheta = fminf(fmaxf(ctheta, CLO), CHI);
    float theta = acosf(ctheta);
    float phi = atan2f(ry, rx);

    float v1x = psx - fix, v1y = psy - fiy, v1z = psz - fiz;
    float v3x = ptx - fjx, v3y = pty - fjy, v3z = ptz - fjz;
    float n1x = v1y * rz - v1z * ry;
    float n1y = v1z * rx - v1x * rz;
    float n1z = v1x * ry - v1y * rx;
    float n2x = ry * v3z - rz * v3y;
    float n2y = rz * v3x - rx * v3z;
    float n2z = rx * v3y - ry * v3x;
    float l1 = sqrtf(n1x * n1x + n1y * n1y + n1z * n1z + 1e-12f) + 1e-8f;
    float l2 = sqrtf(n2x * n2x + n2y * n2y + n2z * n2z + 1e-12f) + 1e-8f;
    float ct = (n1x * n2x + n1y * n2y + n1z * n2z) / (l1 * l2);
    ct = fminf(fmaxf(ct, CLO), CHI);
    float tau = acosf(ct);

    int slot = atomicAdd(&g_cursor[t], 1);
    g_csrc[slot] = s;
    g_cgeo[slot] = make_float4(d, theta, phi, tau);
}

// ---------------------------------------------------------------------------
// Pre-aggregation: warp per node. AggX, U1, U2 in registers (2 cols/lane).
__global__ __launch_bounds__(256) void k_preagg(
    const float* __restrict__ x,
    const float* __restrict__ aw1, const float* __restrict__ ab1,
    const float* __restrict__ aw2, const float* __restrict__ ab2, int N) {
    int warp = (blockIdx.x * blockDim.x + threadIdx.x) >> 5;
    int lane = threadIdx.x & 31;
    if (warp >= N) return;
    int i = warp;
    int c0 = 2 * lane;

    unsigned long long W1[4], W2[4];
#pragma unroll
    for (int k = 0; k < 4; k++) {
        float2 a = *(const float2*)(aw1 + k * 64 + c0);
        float2 b = *(const float2*)(aw2 + k * 64 + c0);
        W1[k] = *(unsigned long long*)&a;
        W2[k] = *(unsigned long long*)&b;
    }
    float2 b1f = *(const float2*)(ab1 + c0);
    float2 b2f = *(const float2*)(ab2 + c0);
    unsigned long long B1 = *(unsigned long long*)&b1f;
    unsigned long long B2 = *(unsigned long long*)&b2f;

    float ax0 = 0.f, ax1 = 0.f, u1a = 0.f, u1b = 0.f, u2a = 0.f, u2b = 0.f;
    int beg = g_csroff[i], end = g_csroff[i + 1];
#pragma unroll 4
    for (int e = beg; e < end; e++) {
        int s = __ldg(&g_csrc[e]);
        float4 g = __ldg(&g_cgeo[e]);
        unsigned long long gx = pk2(g.x), gy = pk2(g.y), gz = pk2(g.z), gw = pk2(g.w);
        unsigned long long t01 = B1, s01 = B2;
        fma2(t01, gx, W1[0], t01);
        fma2(t01, gy, W1[1], t01);
        fma2(t01, gz, W1[2], t01);
        fma2(t01, gw, W1[3], t01);
        fma2(s01, gx, W2[0], s01);
        fma2(s01, gy, W2[1], s01);
        fma2(s01, gz, W2[2], s01);
        fma2(s01, gw, W2[3], s01);
        float t0, t1, s0, s1;
        unpk2(t01, t0, t1);
        unpk2(s01, s0, s1);
        u1a += fmaxf(t0, 0.f);
        u1b += fmaxf(t1, 0.f);
        u2a += fmaxf(s0, 0.f);
        u2b += fmaxf(s1, 0.f);
        float2 xv = __ldg((const float2*)(x + (size_t)s * 64 + c0));
        ax0 += xv.x;
        ax1 += xv.y;
    }
    *(float2*)(g_bufA + (size_t)i * 64 + c0) = make_float2(ax0, ax1);
    *(float2*)(g_bufU1 + (size_t)i * 64 + c0) = make_float2(u1a, u1b);
    *(float2*)(g_bufU2 + (size_t)i * 64 + c0) = make_float2(u2a, u2b);
}

// Second aggregation: warp per node, sum h1[src]
__global__ __launch_bounds__(256) void k_agg2(int N) {
    int warp = (blockIdx.x * blockDim.x + threadIdx.x) >> 5;
    int lane = threadIdx.x & 31;
    if (warp >= N) return;
    int i = warp;
    int c0 = 2 * lane;
    float a0 = 0.f, a1 = 0.f;
    int beg = g_csroff[i], end = g_csroff[i + 1];
#pragma unroll 4
    for (int e = beg; e < end; e++) {
        int s = __ldg(&g_csrc[e]);
        float2 hv = *(const float2*)(g_h1 + (size_t)s * 64 + c0);
        a0 += hv.x;
        a1 += hv.y;
    }
    *(float2*)(g_agg + (size_t)i * 64 + c0) = make_float2(a0, a1);
}

// ---------------------------------------------------------------------------
// Generic node GEMM: Out = relu(A@WA (+ B@WB) + (bias1+bias2)*scale)
// k-chunk = 32 (8 barriers per block). FFMA2 inner loop.
__global__ __launch_bounds__(256) void k_gemm(
    const float* __restrict__ A, const float* __restrict__ WA,
    const float* __restrict__ B, const float* __restrict__ WB,
    const float* __restrict__ bias1, const float* __restrict__ bias2,
    int useDeg, float* __restrict__ Out, const int* __restrict__ batch, int N) {
    __shared__ float As[32][130];
    __shared__ float Ws[32][64];
    int t = threadIdx.x;
    int lane = t & 31;
    int wq = t >> 5;
    int rowBase = blockIdx.x * 128;
    int c = wq * 8;
    unsigned long long acc2[4][4];
#pragma unroll
    for (int ri = 0; ri < 4; ri++)
#pragma unroll
        for (int p = 0; p < 4; p++) acc2[ri][p] = 0ULL;

    for (int ph = 0; ph < 2; ph++) {
        const float* Ap = ph ? B : A;
        const float* Wp = ph ? WB : WA;
        if (Ap == nullptr) break;
        for (int k0 = 0; k0 < 64; k0 += 32) {
            __syncthreads();
#pragma unroll
            for (int it = 0; it < 4; it++) {
                int idx = t + 256 * it;
                int row = idx >> 3;       // 128 rows
                int k4 = idx & 7;         // 8 float4 per 32-col chunk
                int gr = rowBase + row;
                float4 v = (gr < N)
                               ? *(const float4*)(Ap + (size_t)gr * 64 + k0 + k4 * 4)
                               : make_float4(0.f, 0.f, 0.f, 0.f);
                As[k4 * 4 + 0][row] = v.x;
                As[k4 * 4 + 1][row] = v.y;
                As[k4 * 4 + 2][row] = v.z;
                As[k4 * 4 + 3][row] = v.w;
            }
#pragma unroll
            for (int it = 0; it < 2; it++) {
                int idx = t + 256 * it;
                int kr = idx >> 4;        // 32 k-rows
                int c4 = idx & 15;        // 16 float4 per 64-col row
                float4 wv = *(const float4*)(Wp + (size_t)(k0 + kr) * 64 + c4 * 4);
                *(float4*)&Ws[kr][c4 * 4] = wv;
            }
            __syncthreads();
#pragma unroll 8
            for (int kk = 0; kk < 32; kk++) {
                unsigned long long ap0 = pk2(As[kk][lane]);
                unsigned long long ap1 = pk2(As[kk][lane + 32]);
                unsigned long long ap2 = pk2(As[kk][lane + 64]);
                unsigned long long ap3 = pk2(As[kk][lane + 96]);
                ulonglong2 wA = *(const ulonglong2*)&Ws[kk][c];
                ulonglong2 wB = *(const ulonglong2*)&Ws[kk][c + 4];
                unsigned long long w[4] = {wA.x, wA.y, wB.x, wB.y};
#pragma unroll
                for (int p = 0; p < 4; p++) {
                    fma2(acc2[0][p], ap0, w[p], acc2[0][p]);
                    fma2(acc2[1][p], ap1, w[p], acc2[1][p]);
                    fma2(acc2[2][p], ap2, w[p], acc2[2][p]);
                    fma2(acc2[3][p], ap3, w[p], acc2[3][p]);
                }
            }
        }
    }

    float bb[8];
#pragma unroll
    for (int j = 0; j < 8; j++)
        bb[j] = bias1[c + j] + (bias2 ? bias2[c + j] : 0.f);

    unsigned fullm = 0xffffffffu;
#pragma unroll
    for (int ri = 0; ri < 4; ri++) {
        int r = rowBase + lane + 32 * ri;
        bool valid = (r < N);
        float o[8];
#pragma unroll
        for (int p = 0; p < 4; p++) unpk2(acc2[ri][p], o[2 * p], o[2 * p + 1]);
        float sc = (valid && useDeg) ? (float)g_degin[r] : 1.0f;
#pragma unroll
        for (int j = 0; j < 8; j++)
            o[j] = valid ? fmaxf(fmaf(bb[j], sc, o[j]), 0.f) : 0.f;

        if (Out) {
            if (valid) {
                *(float4*)(Out + (size_t)r * 64 + c) = make_float4(o[0], o[1], o[2], o[3]);
                *(float4*)(Out + (size_t)r * 64 + c + 4) = make_float4(o[4], o[5], o[6], o[7]);
            }
        } else {
            int b = valid ? batch[r] : -1;
            int b0 = __shfl_sync(fullm, b, 0);
            bool uniform = __all_sync(fullm, b == b0);
            if (uniform) {
                if (b0 >= 0) {
#pragma unroll
                    for (int j = 0; j < 8; j++) {
                        float v = o[j];
#pragma unroll
                        for (int off = 16; off; off >>= 1)
                            v += __shfl_xor_sync(fullm, v, off);
                        if (lane == 0) atomicAdd(&g_pool[b0 * 64 + c + j], v);
                    }
                }
            } else if (valid) {
#pragma unroll
                for (int j = 0; j < 8; j++)
                    atomicAdd(&g_pool[b * 64 + c + j], o[j]);
            }
        }
    }
}

// ---------------------------------------------------------------------------
// Final: g = pool/cnt ; relu(g@l1w+l1b) @ l2w + l2b
__global__ void k_final(const float* __restrict__ l1w, const float* __restrict__ l1b,
                        const float* __restrict__ l2w, const float* __restrict__ l2b,
                        float* __restrict__ out, int G) {
    __shared__ float gm[GMAX * 64];
    __shared__ float z1[GMAX * 32];
    int t = threadIdx.x;
    for (int idx = t; idx < G * 64; idx += blockDim.x) {
        int b = idx / 64;
        float cnt = fmaxf((float)g_cnt[b], 1.0f);
        gm[idx] = g_pool[idx] / cnt;
    }
    __syncthreads();
    for (int idx = t; idx < G * 32; idx += blockDim.x) {
        int b = idx / 32, j = idx % 32;
        float s = l1b[j];
#pragma unroll
        for (int k = 0; k < 64; k++) s = fmaf(gm[b * 64 + k], l1w[k * 32 + j], s);
        z1[idx] = fmaxf(s, 0.f);
    }
    __syncthreads();
    if (t < G) {
        float s = l2b[0];
#pragma unroll
        for (int j = 0; j < 32; j++) s = fmaf(z1[t * 32 + j], l2w[j], s);
        out[t] = s;
    }
}

// ---------------------------------------------------------------------------
extern "C" void kernel_launch(void* const* d_in, const int* in_sizes, int n_in,
                              void* d_out, int out_size) {
    const float* x    = (const float*)d_in[0];
    const int*   eix  = (const int*)d_in[1];
    const int*   batch= (const int*)d_in[2];
    const float* pos  = (const float*)d_in[3];
    const float* c1lw = (const float*)d_in[4];
    const float* c1lb = (const float*)d_in[5];
    const float* c1aw = (const float*)d_in[6];
    const float* c1ab = (const float*)d_in[7];
    const float* c1bw = (const float*)d_in[8];
    const float* c1bb = (const float*)d_in[9];
    const float* c2lw = (const float*)d_in[10];
    const float* c2lb = (const float*)d_in[11];
    const float* c2aw = (const float*)d_in[12];
    const float* c2ab = (const float*)d_in[13];
    const float* c2bw = (const float*)d_in[14];
    const float* c2bb = (const float*)d_in[15];
    const float* saw  = (const float*)d_in[16];
    const float* sab  = (const float*)d_in[17];
    const float* l1w  = (const float*)d_in[18];
    const float* l1b  = (const float*)d_in[19];
    const float* l2w  = (const float*)d_in[20];
    const float* l2b  = (const float*)d_in[21];

    int N = in_sizes[0] / 64;
    int E = in_sizes[1] / 2;
    int G = out_size;
    const int* src = eix;
    const int* dst = eix + E;
    float* out = (float*)d_out;

    void *pA, *pU1, *pU2, *pAgg, *pH1, *pH2;
    cudaGetSymbolAddress(&pA, g_bufA);
    cudaGetSymbolAddress(&pU1, g_bufU1);
    cudaGetSymbolAddress(&pU2, g_bufU2);
    cudaGetSymbolAddress(&pAgg, g_agg);
    cudaGetSymbolAddress(&pH1, g_h1);
    cudaGetSymbolAddress(&pH2, g_h2);

    int nbN = (N + 255) / 256;
    int nbE = (E + 255) / 256;
    int nbScan = (N + SCANB - 1) / SCANB;

    k_init<<<nbN, 256>>>(N);
    k_edge1<<<nbE, 256>>>(src, dst, pos, E);
    k_edge2<<<nbE, 256>>>(src, E);
    k_node<<<nbN, 256>>>(dst, batch, N);
    k_scanA<<<nbScan, SCANB>>>(N);
    k_scanB<<<1, 256>>>(nbScan);
    k_scanC<<<nbN, 256>>>(N);
    k_geo<<<nbE, 256>>>(src, dst, pos, E);
    k_preagg<<<(N + 7) / 8, 256>>>(x, c1aw, c1ab, c2aw, c2ab, N);

    int nbG = (N + 127) / 128;
    // conv1: h1 = relu(AggX@c1lw + U1@c1bw + deg_in*(c1lb+c1bb))
    k_gemm<<<nbG, 256>>>((const float*)pA, c1lw, (const float*)pU1, c1bw,
                         c1lb, c1bb, 1, (float*)pH1, batch, N);
    // aggregate h1 over in-edges
    k_agg2<<<(N + 7) / 8, 256>>>(N);
    // conv2: h2 = relu(AggH@c2lw + U2@c2bw + deg_in*(c2lb+c2bb))
    k_gemm<<<nbG, 256>>>((const float*)pAgg, c2lw, (const float*)pU2, c2bw,
                         c2lb, c2bb, 1, (float*)pH2, batch, N);
    // score layer + fused mean-pool numerator (warp-reduced atomics)
    k_gemm<<<nbG, 256>>>((const float*)pH2, saw, nullptr, nullptr,
                         sab, nullptr, 0, nullptr, batch, N);
    k_final<<<1, 1024>>>(l1w, l1b, l2w, l2b, out, G);
}

// round 8
// speedup vs baseline: 1.0798x; 1.0798x over previous
#include <cuda_runtime.h>
#include <math.h>
#include <stdint.h>

// ============================================================================
// ComENet-style GNN forward (R8): exact R6 base (395.6us) + ONE change:
//  - conv2 GEMM and score GEMM + mean-pool fused into one kernel
//    (h2 never written to global; score GEMM runs from smem-staged h2 tile)
// ============================================================================

#define NMAX 100480
#define EMAX 1610000
#define GMAX 64
#define SCANB 1024

__device__ unsigned long long g_key1[NMAX];
__device__ unsigned long long g_key2[NMAX];
__device__ unsigned long long g_ekey[EMAX];
__device__ int   g_degin[NMAX];
__device__ int   g_nnA[NMAX];
__device__ int   g_nnB[NMAX];
__device__ int   g_incl[NMAX];
__device__ int   g_bsum[256];
__device__ int   g_boff[256];
__device__ int   g_csroff[NMAX + 1];
__device__ int   g_cursor[NMAX];
__device__ int   g_csrc[EMAX];
__device__ float4 g_cgeo[EMAX];
__device__ float g_bufA[NMAX * 64];   // sum x[src]
__device__ float g_bufU1[NMAX * 64];  // sum relu(geo@c1aw+c1ab)
__device__ float g_bufU2[NMAX * 64];  // sum relu(geo@c2aw+c2ab)
__device__ float g_agg[NMAX * 64];    // sum h1[src]
__device__ float g_h1[NMAX * 64];
__device__ float g_pool[GMAX * 64];
__device__ int   g_cnt[GMAX];

// ---- packed fp32x2 helpers (Blackwell FFMA2, PTX-only) ---------------------
__device__ __forceinline__ unsigned long long pk2(float v) {
    unsigned long long r;
    unsigned u = __float_as_uint(v);
    asm("mov.b64 %0, {%1, %1};" : "=l"(r) : "r"(u));
    return r;
}
__device__ __forceinline__ void fma2(unsigned long long& d, unsigned long long a,
                                     unsigned long long b, unsigned long long c) {
    asm("fma.rn.f32x2 %0, %1, %2, %3;" : "=l"(d) : "l"(a), "l"(b), "l"(c));
}
__device__ __forceinline__ void unpk2(unsigned long long v, float& lo, float& hi) {
    unsigned a, b;
    asm("mov.b64 {%0, %1}, %2;" : "=r"(a), "=r"(b) : "l"(v));
    lo = __uint_as_float(a);
    hi = __uint_as_float(b);
}

// ---------------------------------------------------------------------------
__global__ void k_init(int n) {
    int i = blockIdx.x * blockDim.x + threadIdx.x;
    if (i < n) {
        g_key1[i] = ~0ULL;
        g_key2[i] = ~0ULL;
        g_degin[i] = 0;
    }
    if (i < GMAX * 64) g_pool[i] = 0.0f;
    if (i < GMAX) g_cnt[i] = 0;
}

// ---------------------------------------------------------------------------
__global__ void k_edge1(const int* __restrict__ src, const int* __restrict__ dst,
                        const float* __restrict__ pos, int E) {
    int e = blockIdx.x * blockDim.x + threadIdx.x;
    if (e >= E) return;
    int s = src[e], t = dst[e];
    float dx = pos[t * 3 + 0] - pos[s * 3 + 0];
    float dy = pos[t * 3 + 1] - pos[s * 3 + 1];
    float dz = pos[t * 3 + 2] - pos[s * 3 + 2];
    float d = sqrtf(dx * dx + dy * dy + dz * dz);
    unsigned long long key =
        (((unsigned long long)__float_as_uint(d)) << 32) | (unsigned int)e;
    g_ekey[e] = key;
    atomicMin(&g_key1[s], key);
    atomicAdd(&g_degin[t], 1);
}

__global__ void k_edge2(const int* __restrict__ src, int E) {
    int e = blockIdx.x * blockDim.x + threadIdx.x;
    if (e >= E) return;
    unsigned long long key = g_ekey[e];
    int s = src[e];
    if (key != g_key1[s]) atomicMin(&g_key2[s], key);
}

__global__ void k_node(const int* __restrict__ dst, const int* __restrict__ batch, int N) {
    int i = blockIdx.x * blockDim.x + threadIdx.x;
    int lane = threadIdx.x & 31;
    int b = -1;
    if (i < N) {
        unsigned long long k1 = g_key1[i];
        g_nnA[i] = (k1 != ~0ULL) ? dst[(int)(k1 & 0xffffffffULL)] : i;
        unsigned long long k2 = g_key2[i];
        g_nnB[i] = (k2 != ~0ULL) ? dst[(int)(k2 & 0xffffffffULL)] : i;
        b = batch[i];
    }
    unsigned m = 0xffffffffu;
    int prev = __shfl_up_sync(m, b, 1);
    bool head = (lane == 0) || (b != prev);
    unsigned hm = __ballot_sync(m, head);
    if (head && b >= 0) {
        unsigned rest = (hm >> lane) >> 1;
        int len = rest ? __ffs(rest) : (32 - lane);
        atomicAdd(&g_cnt[b], len);
    }
}

// ---------------------------------------------------------------------------
__global__ void k_scanA(int N) {
    __shared__ int wsum[32];
    int b = blockIdx.x, t = threadIdx.x;
    int i = b * SCANB + t;
    int lane = t & 31, w = t >> 5;
    int v = (i < N) ? g_degin[i] : 0;
    int x = v;
#pragma unroll
    for (int o = 1; o < 32; o <<= 1) {
        int y = __shfl_up_sync(~0u, x, o);
        if (lane >= o) x += y;
    }
    if (lane == 31) wsum[w] = x;
    __syncthreads();
    if (w == 0) {
        int z = wsum[lane];
#pragma unroll
        for (int o = 1; o < 32; o <<= 1) {
            int y = __shfl_up_sync(~0u, z, o);
            if (lane >= o) z += y;
        }
        wsum[lane] = z;
    }
    __syncthreads();
    int off = (w > 0) ? wsum[w - 1] : 0;
    int incl = x + off;
    if (i < N) g_incl[i] = incl;
    if (t == SCANB - 1) g_bsum[b] = incl;
}

__global__ void k_scanB(int nb) {
    __shared__ int sh[256];
    int t = threadIdx.x;
    if (t < nb) sh[t] = g_bsum[t];
    __syncthreads();
    if (t == 0) {
        int run = 0;
        for (int b = 0; b < nb; b++) {
            int v = sh[b];
            sh[b] = run;
            run += v;
        }
    }
    __syncthreads();
    if (t < nb) g_boff[t] = sh[t];
}

__global__ void k_scanC(int N) {
    int i = blockIdx.x * blockDim.x + threadIdx.x;
    if (i >= N) return;
    int b = i / SCANB;
    int tot = g_incl[i] + g_boff[b];
    g_csroff[i + 1] = tot;
    g_cursor[i] = tot - g_degin[i];
    if (i == 0) g_csroff[0] = 0;
}

// ---------------------------------------------------------------------------
__global__ void k_geo(const int* __restrict__ src, const int* __restrict__ dst,
                      const float* __restrict__ pos, int E) {
    int e = blockIdx.x * blockDim.x + threadIdx.x;
    if (e >= E) return;
    int s = src[e], t = dst[e];
    float psx = pos[s * 3 + 0], psy = pos[s * 3 + 1], psz = pos[s * 3 + 2];
    float ptx = pos[t * 3 + 0], pty = pos[t * 3 + 1], ptz = pos[t * 3 + 2];

    int nAs = g_nnA[s];
    int fi = (nAs != t) ? nAs : g_nnB[s];
    int nAt = g_nnA[t];
    int fj = (nAt != s) ? nAt : g_nnB[t];

    float fix = pos[fi * 3 + 0], fiy = pos[fi * 3 + 1], fiz = pos[fi * 3 + 2];
    float fjx = pos[fj * 3 + 0], fjy = pos[fj * 3 + 1], fjz = pos[fj * 3 + 2];

    float rx = ptx - psx, ry = pty - psy, rz = ptz - psz;
    float d = sqrtf(rx * rx + ry * ry + rz * rz);

    const float CLO = -1.0f + 1e-8f;
    const float CHI = 1.0f - 1e-8f;
    float ctheta = rz / (d + 1e-8f);
    ctheta = fminf(fmaxf(ctheta, CLO), CHI);
    float theta = acosf(ctheta);
    float phi = atan2f(ry, rx);

    float v1x = psx - fix, v1y = psy - fiy, v1z = psz - fiz;
    float v3x = ptx - fjx, v3y = pty - fjy, v3z = ptz - fjz;
    float n1x = v1y * rz - v1z * ry;
    float n1y = v1z * rx - v1x * rz;
    float n1z = v1x * ry - v1y * rx;
    float n2x = ry * v3z - rz * v3y;
    float n2y = rz * v3x - rx * v3z;
    float n2z = rx * v3y - ry * v3x;
    float l1 = sqrtf(n1x * n1x + n1y * n1y + n1z * n1z + 1e-12f) + 1e-8f;
    float l2 = sqrtf(n2x * n2x + n2y * n2y + n2z * n2z + 1e-12f) + 1e-8f;
    float ct = (n1x * n2x + n1y * n2y + n1z * n2z) / (l1 * l2);
    ct = fminf(fmaxf(ct, CLO), CHI);
    float tau = acosf(ct);

    int slot = atomicAdd(&g_cursor[t], 1);
    g_csrc[slot] = s;
    g_cgeo[slot] = make_float4(d, theta, phi, tau);
}

// ---------------------------------------------------------------------------
__global__ __launch_bounds__(256) void k_preagg(
    const float* __restrict__ x,
    const float* __restrict__ aw1, const float* __restrict__ ab1,
    const float* __restrict__ aw2, const float* __restrict__ ab2, int N) {
    int warp = (blockIdx.x * blockDim.x + threadIdx.x) >> 5;
    int lane = threadIdx.x & 31;
    if (warp >= N) return;
    int i = warp;
    int c0 = 2 * lane;

    unsigned long long W1[4], W2[4];
#pragma unroll
    for (int k = 0; k < 4; k++) {
        float2 a = *(const float2*)(aw1 + k * 64 + c0);
        float2 b = *(const float2*)(aw2 + k * 64 + c0);
        W1[k] = *(unsigned long long*)&a;
        W2[k] = *(unsigned long long*)&b;
    }
    float2 b1f = *(const float2*)(ab1 + c0);
    float2 b2f = *(const float2*)(ab2 + c0);
    unsigned long long B1 = *(unsigned long long*)&b1f;
    unsigned long long B2 = *(unsigned long long*)&b2f;

    float ax0 = 0.f, ax1 = 0.f, u1a = 0.f, u1b = 0.f, u2a = 0.f, u2b = 0.f;
    int beg = g_csroff[i], end = g_csroff[i + 1];
#pragma unroll 4
    for (int e = beg; e < end; e++) {
        int s = g_csrc[e];
        float4 g = g_cgeo[e];
        unsigned long long gx = pk2(g.x), gy = pk2(g.y), gz = pk2(g.z), gw = pk2(g.w);
        unsigned long long t01 = B1, s01 = B2;
        fma2(t01, gx, W1[0], t01);
        fma2(t01, gy, W1[1], t01);
        fma2(t01, gz, W1[2], t01);
        fma2(t01, gw, W1[3], t01);
        fma2(s01, gx, W2[0], s01);
        fma2(s01, gy, W2[1], s01);
        fma2(s01, gz, W2[2], s01);
        fma2(s01, gw, W2[3], s01);
        float t0, t1, s0, s1;
        unpk2(t01, t0, t1);
        unpk2(s01, s0, s1);
        u1a += fmaxf(t0, 0.f);
        u1b += fmaxf(t1, 0.f);
        u2a += fmaxf(s0, 0.f);
        u2b += fmaxf(s1, 0.f);
        float2 xv = *(const float2*)(x + (size_t)s * 64 + c0);
        ax0 += xv.x;
        ax1 += xv.y;
    }
    *(float2*)(g_bufA + (size_t)i * 64 + c0) = make_float2(ax0, ax1);
    *(float2*)(g_bufU1 + (size_t)i * 64 + c0) = make_float2(u1a, u1b);
    *(float2*)(g_bufU2 + (size_t)i * 64 + c0) = make_float2(u2a, u2b);
}

__global__ __launch_bounds__(256) void k_agg2(int N) {
    int warp = (blockIdx.x * blockDim.x + threadIdx.x) >> 5;
    int lane = threadIdx.x & 31;
    if (warp >= N) return;
    int i = warp;
    int c0 = 2 * lane;
    float a0 = 0.f, a1 = 0.f;
    int beg = g_csroff[i], end = g_csroff[i + 1];
#pragma unroll 4
    for (int e = beg; e < end; e++) {
        int s = g_csrc[e];
        float2 hv = *(const float2*)(g_h1 + (size_t)s * 64 + c0);
        a0 += hv.x;
        a1 += hv.y;
    }
    *(float2*)(g_agg + (size_t)i * 64 + c0) = make_float2(a0, a1);
}

// ---------------------------------------------------------------------------
// conv1 GEMM (R6 form, k-chunk 16): h1 = relu(A@WA + B@WB + deg*(b1+b2))
__global__ __launch_bounds__(256) void k_gemm(
    const float* __restrict__ A, const float* __restrict__ WA,
    const float* __restrict__ B, const float* __restrict__ WB,
    const float* __restrict__ bias1, const float* __restrict__ bias2,
    float* __restrict__ Out, int N) {
    __shared__ float As[16][130];
    __shared__ float Ws[16][64];
    int t = threadIdx.x;
    int lane = t & 31;
    int wq = t >> 5;
    int rowBase = blockIdx.x * 128;
    int c = wq * 8;
    unsigned long long acc2[4][4];
#pragma unroll
    for (int ri = 0; ri < 4; ri++)
#pragma unroll
        for (int p = 0; p < 4; p++) acc2[ri][p] = 0ULL;

    for (int ph = 0; ph < 2; ph++) {
        const float* Ap = ph ? B : A;
        const float* Wp = ph ? WB : WA;
        for (int k0 = 0; k0 < 64; k0 += 16) {
            __syncthreads();
#pragma unroll
            for (int it = 0; it < 2; it++) {
                int idx = t + 256 * it;
                int row = idx >> 2;
                int k4 = idx & 3;
                int gr = rowBase + row;
                float4 v = (gr < N)
                               ? *(const float4*)(Ap + (size_t)gr * 64 + k0 + k4 * 4)
                               : make_float4(0.f, 0.f, 0.f, 0.f);
                As[k4 * 4 + 0][row] = v.x;
                As[k4 * 4 + 1][row] = v.y;
                As[k4 * 4 + 2][row] = v.z;
                As[k4 * 4 + 3][row] = v.w;
            }
            {
                int kr = t >> 4;
                int c4 = t & 15;
                float4 wv = *(const float4*)(Wp + (size_t)(k0 + kr) * 64 + c4 * 4);
                *(float4*)&Ws[kr][c4 * 4] = wv;
            }
            __syncthreads();
#pragma unroll
            for (int kk = 0; kk < 16; kk++) {
                unsigned long long ap0 = pk2(As[kk][lane]);
                unsigned long long ap1 = pk2(As[kk][lane + 32]);
                unsigned long long ap2 = pk2(As[kk][lane + 64]);
                unsigned long long ap3 = pk2(As[kk][lane + 96]);
                ulonglong2 wA = *(const ulonglong2*)&Ws[kk][c];
                ulonglong2 wB = *(const ulonglong2*)&Ws[kk][c + 4];
                unsigned long long w[4] = {wA.x, wA.y, wB.x, wB.y};
#pragma unroll
                for (int p = 0; p < 4; p++) {
                    fma2(acc2[0][p], ap0, w[p], acc2[0][p]);
                    fma2(acc2[1][p], ap1, w[p], acc2[1][p]);
                    fma2(acc2[2][p], ap2, w[p], acc2[2][p]);
                    fma2(acc2[3][p], ap3, w[p], acc2[3][p]);
                }
            }
        }
    }

    float bb[8];
#pragma unroll
    for (int j = 0; j < 8; j++)
        bb[j] = bias1[c + j] + bias2[c + j];

#pragma unroll
    for (int ri = 0; ri < 4; ri++) {
        int r = rowBase + lane + 32 * ri;
        if (r >= N) continue;
        float o[8];
#pragma unroll
        for (int p = 0; p < 4; p++) unpk2(acc2[ri][p], o[2 * p], o[2 * p + 1]);
        float sc = (float)g_degin[r];
#pragma unroll
        for (int j = 0; j < 8; j++) o[j] = fmaxf(fmaf(bb[j], sc, o[j]), 0.f);
        *(float4*)(Out + (size_t)r * 64 + c) = make_float4(o[0], o[1], o[2], o[3]);
        *(float4*)(Out + (size_t)r * 64 + c + 4) = make_float4(o[4], o[5], o[6], o[7]);
    }
}

// ---------------------------------------------------------------------------
// Fused conv2 + score + mean-pool:
//   h2 = relu(Agg@c2lw + U2@c2bw + deg*(c2lb+c2bb))   (stays in smem)
//   sc = relu(h2@saw + sab) ; pool[batch] += sc (warp-reduced)
__global__ __launch_bounds__(256) void k_conv2score(
    const float* __restrict__ A, const float* __restrict__ WA,
    const float* __restrict__ B, const float* __restrict__ WB,
    const float* __restrict__ bias1, const float* __restrict__ bias2,
    const float* __restrict__ saw, const float* __restrict__ sab,
    const int* __restrict__ batch, int N) {
    // smem pool: phase1 uses [0 .. 16*130) As + [16*130 .. 16*130+16*64) Ws
    //            phase2 uses [0 .. 64*130) Hs + [64*130 .. +64*64) Ws_sc
    __shared__ float sp[64 * 130 + 64 * 64];
    float* AsW = sp + 64 * 130;  // 16*64 weight stage (phase 1) / saw (phase 2)
    int t = threadIdx.x;
    int lane = t & 31;
    int wq = t >> 5;
    int rowBase = blockIdx.x * 128;
    int c = wq * 8;
    unsigned long long acc2[4][4];
#pragma unroll
    for (int ri = 0; ri < 4; ri++)
#pragma unroll
        for (int p = 0; p < 4; p++) acc2[ri][p] = 0ULL;

    // ---- phase 1: conv2 mainloop (identical math to k_gemm) ----
    for (int ph = 0; ph < 2; ph++) {
        const float* Ap = ph ? B : A;
        const float* Wp = ph ? WB : WA;
        for (int k0 = 0; k0 < 64; k0 += 16) {
            __syncthreads();
#pragma unroll
            for (int it = 0; it < 2; it++) {
                int idx = t + 256 * it;
                int row = idx >> 2;
                int k4 = idx & 3;
                int gr = rowBase + row;
                float4 v = (gr < N)
                               ? *(const float4*)(Ap + (size_t)gr * 64 + k0 + k4 * 4)
                               : make_float4(0.f, 0.f, 0.f, 0.f);
                sp[(k4 * 4 + 0) * 130 + row] = v.x;
                sp[(k4 * 4 + 1) * 130 + row] = v.y;
                sp[(k4 * 4 + 2) * 130 + row] = v.z;
                sp[(k4 * 4 + 3) * 130 + row] = v.w;
            }
            {
                int kr = t >> 4;
                int c4 = t & 15;
                float4 wv = *(const float4*)(Wp + (size_t)(k0 + kr) * 64 + c4 * 4);
                *(float4*)&AsW[kr * 64 + c4 * 4] = wv;
            }
            __syncthreads();
#pragma unroll
            for (int kk = 0; kk < 16; kk++) {
                unsigned long long ap0 = pk2(sp[kk * 130 + lane]);
                unsigned long long ap1 = pk2(sp[kk * 130 + lane + 32]);
                unsigned long long ap2 = pk2(sp[kk * 130 + lane + 64]);
                unsigned long long ap3 = pk2(sp[kk * 130 + lane + 96]);
                ulonglong2 wA = *(const ulonglong2*)&AsW[kk * 64 + c];
                ulonglong2 wB = *(const ulonglong2*)&AsW[kk * 64 + c + 4];
                unsigned long long w[4] = {wA.x, wA.y, wB.x, wB.y};
#pragma unroll
                for (int p = 0; p < 4; p++) {
                    fma2(acc2[0][p], ap0, w[p], acc2[0][p]);
                    fma2(acc2[1][p], ap1, w[p], acc2[1][p]);
                    fma2(acc2[2][p], ap2, w[p], acc2[2][p]);
                    fma2(acc2[3][p], ap3, w[p], acc2[3][p]);
                }
            }
        }
    }

    // ---- h2 epilogue -> smem Hs[k=col][row] ----
    float bb[8];
#pragma unroll
    for (int j = 0; j < 8; j++)
        bb[j] = bias1[c + j] + bias2[c + j];

    __syncthreads();  // done reading phase-1 As before overwriting with Hs
#pragma unroll
    for (int ri = 0; ri < 4; ri++) {
        int r = rowBase + lane + 32 * ri;
        bool valid = (r < N);
        float o[8];
#pragma unroll
        for (int p = 0; p < 4; p++) unpk2(acc2[ri][p], o[2 * p], o[2 * p + 1]);
        float sc = valid ? (float)g_degin[r] : 0.f;
#pragma unroll
        for (int j = 0; j < 8; j++) {
            o[j] = valid ? fmaxf(fmaf(bb[j], sc, o[j]), 0.f) : 0.f;
            sp[(c + j) * 130 + lane + 32 * ri] = o[j];
        }
    }
    // stage saw [64x64] into AsW
#pragma unroll
    for (int it = 0; it < 4; it++) {
        int idx = t + 256 * it;          // 0..1023 float4s
        *(float4*)&AsW[idx * 4] = *(const float4*)(saw + idx * 4);
    }
    __syncthreads();

    // ---- phase 2: score GEMM from smem ----
    unsigned long long accs[4][4];
#pragma unroll
    for (int ri = 0; ri < 4; ri++)
#pragma unroll
        for (int p = 0; p < 4; p++) accs[ri][p] = 0ULL;

#pragma unroll 8
    for (int kk = 0; kk < 64; kk++) {
        unsigned long long ap0 = pk2(sp[kk * 130 + lane]);
        unsigned long long ap1 = pk2(sp[kk * 130 + lane + 32]);
        unsigned long long ap2 = pk2(sp[kk * 130 + lane + 64]);
        unsigned long long ap3 = pk2(sp[kk * 130 + lane + 96]);
        ulonglong2 wA = *(const ulonglong2*)&AsW[kk * 64 + c];
        ulonglong2 wB = *(const ulonglong2*)&AsW[kk * 64 + c + 4];
        unsigned long long w[4] = {wA.x, wA.y, wB.x, wB.y};
#pragma unroll
        for (int p = 0; p < 4; p++) {
            fma2(accs[0][p], ap0, w[p], accs[0][p]);
            fma2(accs[1][p], ap1, w[p], accs[1][p]);
            fma2(accs[2][p], ap2, w[p], accs[2][p]);
            fma2(accs[3][p], ap3, w[p], accs[3][p]);
        }
    }

    float sb[8];
#pragma unroll
    for (int j = 0; j < 8; j++) sb[j] = sab[c + j];

    unsigned fullm = 0xffffffffu;
#pragma unroll
    for (int ri = 0; ri < 4; ri++) {
        int r = rowBase + lane + 32 * ri;
        bool valid = (r < N);
        float o[8];
#pragma unroll
        for (int p = 0; p < 4; p++) unpk2(accs[ri][p], o[2 * p], o[2 * p + 1]);
#pragma unroll
        for (int j = 0; j < 8; j++)
            o[j] = valid ? fmaxf(o[j] + sb[j], 0.f) : 0.f;

        int b = valid ? batch[r] : -1;
        int b0 = __shfl_sync(fullm, b, 0);
        bool uniform = __all_sync(fullm, b == b0);
        if (uniform) {
            if (b0 >= 0) {
#pragma unroll
                for (int j = 0; j < 8; j++) {
                    float v = o[j];
#pragma unroll
                    for (int off = 16; off; off >>= 1)
                        v += __shfl_xor_sync(fullm, v, off);
                    if (lane == 0) atomicAdd(&g_pool[b0 * 64 + c + j], v);
                }
            }
        } else if (valid) {
#pragma unroll
            for (int j = 0; j < 8; j++)
                atomicAdd(&g_pool[b * 64 + c + j], o[j]);
        }
    }
}

// ---------------------------------------------------------------------------
__global__ void k_final(const float* __restrict__ l1w, const float* __restrict__ l1b,
                        const float* __restrict__ l2w, const float* __restrict__ l2b,
                        float* __restrict__ out, int G) {
    __shared__ float gm[GMAX * 64];
    __shared__ float z1[GMAX * 32];
    int t = threadIdx.x;
    for (int idx = t; idx < G * 64; idx += blockDim.x) {
        int b = idx / 64;
        float cnt = fmaxf((float)g_cnt[b], 1.0f);
        gm[idx] = g_pool[idx] / cnt;
    }
    __syncthreads();
    for (int idx = t; idx < G * 32; idx += blockDim.x) {
        int b = idx / 32, j = idx % 32;
        float s = l1b[j];
#pragma unroll
        for (int k = 0; k < 64; k++) s = fmaf(gm[b * 64 + k], l1w[k * 32 + j], s);
        z1[idx] = fmaxf(s, 0.f);
    }
    __syncthreads();
    if (t < G) {
        float s = l2b[0];
#pragma unroll
        for (int j = 0; j < 32; j++) s = fmaf(z1[t * 32 + j], l2w[j], s);
        out[t] = s;
    }
}

// ---------------------------------------------------------------------------
extern "C" void kernel_launch(void* const* d_in, const int* in_sizes, int n_in,
                              void* d_out, int out_size) {
    const float* x    = (const float*)d_in[0];
    const int*   eix  = (const int*)d_in[1];
    const int*   batch= (const int*)d_in[2];
    const float* pos  = (const float*)d_in[3];
    const float* c1lw = (const float*)d_in[4];
    const float* c1lb = (const float*)d_in[5];
    const float* c1aw = (const float*)d_in[6];
    const float* c1ab = (const float*)d_in[7];
    const float* c1bw = (const float*)d_in[8];
    const float* c1bb = (const float*)d_in[9];
    const float* c2lw = (const float*)d_in[10];
    const float* c2lb = (const float*)d_in[11];
    const float* c2aw = (const float*)d_in[12];
    const float* c2ab = (const float*)d_in[13];
    const float* c2bw = (const float*)d_in[14];
    const float* c2bb = (const float*)d_in[15];
    const float* saw  = (const float*)d_in[16];
    const float* sab  = (const float*)d_in[17];
    const float* l1w  = (const float*)d_in[18];
    const float* l1b  = (const float*)d_in[19];
    const float* l2w  = (const float*)d_in[20];
    const float* l2b  = (const float*)d_in[21];

    int N = in_sizes[0] / 64;
    int E = in_sizes[1] / 2;
    int G = out_size;
    const int* src = eix;
    const int* dst = eix + E;
    float* out = (float*)d_out;

    void *pA, *pU1, *pU2, *pAgg, *pH1;
    cudaGetSymbolAddress(&pA, g_bufA);
    cudaGetSymbolAddress(&pU1, g_bufU1);
    cudaGetSymbolAddress(&pU2, g_bufU2);
    cudaGetSymbolAddress(&pAgg, g_agg);
    cudaGetSymbolAddress(&pH1, g_h1);

    int nbN = (N + 255) / 256;
    int nbE = (E + 255) / 256;
    int nbScan = (N + SCANB - 1) / SCANB;

    k_init<<<nbN, 256>>>(N);
    k_edge1<<<nbE, 256>>>(src, dst, pos, E);
    k_edge2<<<nbE, 256>>>(src, E);
    k_node<<<nbN, 256>>>(dst, batch, N);
    k_scanA<<<nbScan, SCANB>>>(N);
    k_scanB<<<1, 256>>>(nbScan);
    k_scanC<<<nbN, 256>>>(N);
    k_geo<<<nbE, 256>>>(src, dst, pos, E);
    k_preagg<<<(N + 7) / 8, 256>>>(x, c1aw, c1ab, c2aw, c2ab, N);

    int nbG = (N + 127) / 128;
    // conv1: h1 = relu(AggX@c1lw + U1@c1bw + deg_in*(c1lb+c1bb))
    k_gemm<<<nbG, 256>>>((const float*)pA, c1lw, (const float*)pU1, c1bw,
                         c1lb, c1bb, (float*)pH1, N);
    // aggregate h1 over in-edges
    k_agg2<<<(N + 7) / 8, 256>>>(N);
    // fused conv2 + score + mean-pool
    k_conv2score<<<nbG, 256>>>((const float*)pAgg, c2lw, (const float*)pU2, c2bw,
                               c2lb, c2bb, saw, sab, batch, N);
    k_final<<<1, 1024>>>(l1w, l1b, l2w, l2b, out, G);
}